// round 13
// baseline (speedup 1.0000x reference)
#include <cuda_runtime.h>
#include <cuda_bf16.h>
#include <mma.h>

using namespace nvcuda;

#define B_ 8
#define C_ 256
#define N_ 4096
#define GROUPS_ 32

// ---------------- scratch (device globals; allocation-free) ----------------
static __device__ __nv_bfloat16 g_hn[(size_t)B_ * N_ * C_];   // 16 MB
static __device__ __nv_bfloat16 g_Q [(size_t)B_ * N_ * C_];
static __device__ __nv_bfloat16 g_K [(size_t)B_ * N_ * C_];
static __device__ __nv_bfloat16 g_V [(size_t)B_ * N_ * C_];
static __device__ __nv_bfloat16 g_H [(size_t)B_ * N_ * C_];
static __device__ __nv_bfloat16 g_wqkv[3 * C_ * C_];
static __device__ __nv_bfloat16 g_wp[C_ * C_];

// ---------------- generic helpers ----------------
__device__ __forceinline__ unsigned smem_u32(const void* p) {
    return (unsigned)__cvta_generic_to_shared(p);
}
__device__ __forceinline__ void cp_async16(void* sdst, const void* gsrc) {
    unsigned sa = smem_u32(sdst);
    asm volatile("cp.async.cg.shared.global [%0], [%1], 16;\n" :: "r"(sa), "l"(gsrc) : "memory");
}
__device__ __forceinline__ void cp_commit() {
    asm volatile("cp.async.commit_group;\n" ::: "memory");
}
__device__ __forceinline__ unsigned pack_bf16(float lo, float hi) {
    unsigned r;
    asm("cvt.rn.bf16x2.f32 %0, %1, %2;" : "=r"(r) : "f"(hi), "f"(lo));
    return r;
}

// ---------------- weight conversion fp32 -> bf16 ----------------
__global__ void convert_weights(const float* __restrict__ wq, const float* __restrict__ wk,
                                const float* __restrict__ wv, const float* __restrict__ wp) {
    int i = blockIdx.x * blockDim.x + threadIdx.x;
    if (i < C_ * C_) {
        g_wqkv[i]               = __float2bfloat16(wq[i]);
        g_wqkv[C_ * C_ + i]     = __float2bfloat16(wk[i]);
        g_wqkv[2 * C_ * C_ + i] = __float2bfloat16(wv[i]);
        g_wp[i]                 = __float2bfloat16(wp[i]);
    }
}

// ---------------- GroupNorm: x[b,c,n] -> hn[b,n,c] (bf16), single DRAM pass --
__global__ void groupnorm_kernel(const float* __restrict__ x,
                                 const float* __restrict__ gamma,
                                 const float* __restrict__ beta) {
    extern __shared__ float xs[];            // 8 * 4096 fp32 = 128 KB
    int bid = blockIdx.x;
    int b = bid >> 5;
    int g = bid & 31;
    const int ELEMS = 8 * N_;                // 32768
    const float* xg = x + ((size_t)(b * C_ + g * 8)) * N_;

    float s = 0.f, s2 = 0.f;
    for (int i = threadIdx.x; i < ELEMS; i += blockDim.x) {
        float v = xg[i];
        xs[i] = v;
        s += v; s2 += v * v;
    }
    __shared__ float sh[64];
    #pragma unroll
    for (int o = 16; o; o >>= 1) {
        s  += __shfl_xor_sync(0xffffffffu, s,  o);
        s2 += __shfl_xor_sync(0xffffffffu, s2, o);
    }
    int w = threadIdx.x >> 5, l = threadIdx.x & 31;
    if (l == 0) { sh[w] = s; sh[32 + w] = s2; }
    __syncthreads();
    if (threadIdx.x < 32) {
        float a = (l < 8) ? sh[l] : 0.f;
        float c = (l < 8) ? sh[32 + l] : 0.f;
        #pragma unroll
        for (int o = 4; o; o >>= 1) {
            a += __shfl_xor_sync(0xffffffffu, a, o);
            c += __shfl_xor_sync(0xffffffffu, c, o);
        }
        if (l == 0) { sh[0] = a; sh[1] = c; }
    }
    __syncthreads();
    float mean = sh[0] * (1.f / ELEMS);
    float var  = sh[1] * (1.f / ELEMS) - mean * mean;
    float rstd = rsqrtf(var + 1e-6f);

    float gm[8], bt[8];
    #pragma unroll
    for (int cl = 0; cl < 8; cl++) { gm[cl] = gamma[g * 8 + cl]; bt[cl] = beta[g * 8 + cl]; }

    __nv_bfloat16* outb = g_hn + (size_t)b * N_ * C_ + g * 8;
    for (int n = threadIdx.x; n < N_; n += blockDim.x) {
        __nv_bfloat16 tmp[8];
        #pragma unroll
        for (int cl = 0; cl < 8; cl++) {
            float v = (xs[cl * N_ + n] - mean) * rstd * gm[cl] + bt[cl];
            tmp[cl] = __float2bfloat16(v);
        }
        *(uint4*)(outb + (size_t)n * C_) = *(uint4*)tmp;
    }
}

// ---------------- 3-stage pipelined WMMA GEMM tiles ----------------
#define BM 128
#define BN 64
#define BK 32
#define LDA_S  (BK + 8)     // 40 halves
#define LDB_S  (BK + 8)
#define LDC_S  (BN + 4)     // 68 floats
#define STAGE_A (BM * LDA_S)            // halves
#define STAGE_B (BN * LDB_S)
#define STAGE_H (STAGE_A + STAGE_B)     // 12800 halves = 25600 B
#define NK (C_ / BK)                    // 8

// smem: max(3 stages = 76800 B, epilogue Csh = 34816 B) -> dynamic 76800
#define GSMEM (3 * STAGE_H * 2)

// MMA block on one stage (identical math to the proven kernel)
#define GEMM_MMA_STAGE(AsP, BsP)                                               \
    do {                                                                       \
        _Pragma("unroll")                                                      \
        for (int ks = 0; ks < 2; ks++) {                                       \
            wmma::fragment<wmma::matrix_a, 16, 16, 16, __nv_bfloat16,          \
                           wmma::row_major> fa[2];                             \
            wmma::fragment<wmma::matrix_b, 16, 16, 16, __nv_bfloat16,          \
                           wmma::col_major> fb[2];                             \
            _Pragma("unroll")                                                  \
            for (int i = 0; i < 2; i++)                                        \
                wmma::load_matrix_sync(fa[i],                                  \
                    (AsP) + (wm * 32 + i * 16) * LDA_S + ks * 16, LDA_S);      \
            _Pragma("unroll")                                                  \
            for (int jj = 0; jj < 2; jj++)                                     \
                wmma::load_matrix_sync(fb[jj],                                 \
                    (BsP) + (wn * 32 + jj * 16) * LDB_S + ks * 16, LDB_S);     \
            _Pragma("unroll")                                                  \
            for (int i = 0; i < 2; i++)                                        \
                _Pragma("unroll")                                              \
                for (int jj = 0; jj < 2; jj++)                                 \
                    wmma::mma_sync(fc[i][jj], fa[i], fb[jj], fc[i][jj]);       \
        }                                                                      \
    } while (0)

// --- fused QKV: C[32768,768] = hn[32768,256] x Wqkv[768,256]^T, routed out ---
__global__ void __launch_bounds__(256)
gemm_qkv(const __nv_bfloat16* __restrict__ Abase,
         const __nv_bfloat16* __restrict__ Bbase,
         __nv_bfloat16* __restrict__ Qo, __nv_bfloat16* __restrict__ Ko,
         __nv_bfloat16* __restrict__ Vo,
         const float* __restrict__ bq, const float* __restrict__ bk,
         const float* __restrict__ bv) {
    extern __shared__ __align__(16) unsigned char smem[];
    __nv_bfloat16* Sh = (__nv_bfloat16*)smem;
    float* Csh = (float*)smem;

    int m0 = blockIdx.x * BM;
    int n0 = blockIdx.y * BN;
    int tid = threadIdx.x;
    int wid = tid >> 5;
    int wm = wid & 3, wn = wid >> 2;

    auto loadstage = [&](int ks) {
        __nv_bfloat16* As = Sh + (ks % 3) * STAGE_H;
        __nv_bfloat16* Bs = As + STAGE_A;
        int k0 = ks * BK;
        #pragma unroll
        for (int v = 0; v < 2; v++) {
            int idx = tid + v * 256;
            int r = idx >> 2, kv = idx & 3;
            cp_async16(As + r * LDA_S + kv * 8,
                       Abase + (size_t)(m0 + r) * C_ + k0 + kv * 8);
        }
        {
            int r = tid >> 2, kv = tid & 3;
            cp_async16(Bs + r * LDB_S + kv * 8,
                       Bbase + (size_t)(n0 + r) * C_ + k0 + kv * 8);
        }
        cp_commit();
    };

    wmma::fragment<wmma::accumulator, 16, 16, 16, float> fc[2][2];
    #pragma unroll
    for (int i = 0; i < 2; i++)
        #pragma unroll
        for (int j = 0; j < 2; j++) wmma::fill_fragment(fc[i][j], 0.f);

    loadstage(0);
    loadstage(1);
    for (int it = 0; it < NK; it++) {
        if (it < NK - 1) asm volatile("cp.async.wait_group 1;\n" ::: "memory");
        else             asm volatile("cp.async.wait_group 0;\n" ::: "memory");
        __syncthreads();
        __nv_bfloat16* As = Sh + (it % 3) * STAGE_H;
        __nv_bfloat16* Bs = As + STAGE_A;
        GEMM_MMA_STAGE(As, Bs);
        if (it + 2 < NK) loadstage(it + 2);
    }
    __syncthreads();

    #pragma unroll
    for (int i = 0; i < 2; i++)
        #pragma unroll
        for (int j = 0; j < 2; j++)
            wmma::store_matrix_sync(Csh + (wm * 32 + i * 16) * LDC_S + wn * 32 + j * 16,
                                    fc[i][j], LDC_S, wmma::mem_row_major);
    __syncthreads();

    int t = n0 >> 8;
    int o0 = n0 & 255;
    const float* bb = (t == 0) ? bq : (t == 1) ? bk : bv;
    float sc = (t == 0) ? 0.0625f : 1.f;
    __nv_bfloat16* dst = (t == 0) ? Qo : (t == 1) ? Ko : Vo;

    #pragma unroll
    for (int it = 0; it < (BM * BN) / 256; it++) {
        int v = tid + it * 256;
        int r = v >> 6, c = v & 63;
        float acc = Csh[r * LDC_S + c];
        dst[(size_t)(m0 + r) * C_ + o0 + c] = __float2bfloat16((acc + bb[o0 + c]) * sc);
    }
}

// --- proj: out[b,o,n] = x + Wp[256,256] @ H[b, n, :]^T + bias[o] ---
__global__ void __launch_bounds__(256)
gemm_proj(const __nv_bfloat16* __restrict__ Abase,   // Wp [256,256]
          const __nv_bfloat16* __restrict__ Bbase,   // H  [b][4096,256]
          float* __restrict__ Obase,
          const float* __restrict__ bias,
          const float* __restrict__ Xres) {
    extern __shared__ __align__(16) unsigned char smem[];
    __nv_bfloat16* Sh = (__nv_bfloat16*)smem;
    float* Csh = (float*)smem;

    int bz = blockIdx.z;
    const __nv_bfloat16* Bm = Bbase + (size_t)bz * N_ * C_;
    int m0 = blockIdx.x * BM;
    int n0 = blockIdx.y * BN;
    int tid = threadIdx.x;
    int wid = tid >> 5;
    int wm = wid & 3, wn = wid >> 2;

    auto loadstage = [&](int ks) {
        __nv_bfloat16* As = Sh + (ks % 3) * STAGE_H;
        __nv_bfloat16* Bs = As + STAGE_A;
        int k0 = ks * BK;
        #pragma unroll
        for (int v = 0; v < 2; v++) {
            int idx = tid + v * 256;
            int r = idx >> 2, kv = idx & 3;
            cp_async16(As + r * LDA_S + kv * 8,
                       Abase + (size_t)(m0 + r) * C_ + k0 + kv * 8);
        }
        {
            int r = tid >> 2, kv = tid & 3;
            cp_async16(Bs + r * LDB_S + kv * 8,
                       Bm + (size_t)(n0 + r) * C_ + k0 + kv * 8);
        }
        cp_commit();
    };

    wmma::fragment<wmma::accumulator, 16, 16, 16, float> fc[2][2];
    #pragma unroll
    for (int i = 0; i < 2; i++)
        #pragma unroll
        for (int j = 0; j < 2; j++) wmma::fill_fragment(fc[i][j], 0.f);

    loadstage(0);
    loadstage(1);
    for (int it = 0; it < NK; it++) {
        if (it < NK - 1) asm volatile("cp.async.wait_group 1;\n" ::: "memory");
        else             asm volatile("cp.async.wait_group 0;\n" ::: "memory");
        __syncthreads();
        __nv_bfloat16* As = Sh + (it % 3) * STAGE_H;
        __nv_bfloat16* Bs = As + STAGE_A;
        GEMM_MMA_STAGE(As, Bs);
        if (it + 2 < NK) loadstage(it + 2);
    }
    __syncthreads();

    #pragma unroll
    for (int i = 0; i < 2; i++)
        #pragma unroll
        for (int j = 0; j < 2; j++)
            wmma::store_matrix_sync(Csh + (wm * 32 + i * 16) * LDC_S + wn * 32 + j * 16,
                                    fc[i][j], LDC_S, wmma::mem_row_major);
    __syncthreads();

    float* O = Obase + (size_t)bz * C_ * N_;
    const float* X = Xres + (size_t)bz * C_ * N_;
    #pragma unroll
    for (int it = 0; it < (BM * BN) / 256; it++) {
        int v = tid + it * 256;
        int r = v >> 6, c = v & 63;
        float acc = Csh[r * LDC_S + c];
        int gr = m0 + r, gc = n0 + c;
        O[(size_t)gr * N_ + gc] = X[(size_t)gr * N_ + gc] + acc + bias[gr];
    }
}

// ---------------- flash PTX helpers ----------------
__device__ __forceinline__ void ldsm4(unsigned addr, unsigned& r0, unsigned& r1,
                                      unsigned& r2, unsigned& r3) {
    asm volatile("ldmatrix.sync.aligned.m8n8.x4.shared.b16 {%0,%1,%2,%3}, [%4];"
                 : "=r"(r0), "=r"(r1), "=r"(r2), "=r"(r3) : "r"(addr));
}
__device__ __forceinline__ void ldsm4t(unsigned addr, unsigned& r0, unsigned& r1,
                                       unsigned& r2, unsigned& r3) {
    asm volatile("ldmatrix.sync.aligned.m8n8.x4.trans.shared.b16 {%0,%1,%2,%3}, [%4];"
                 : "=r"(r0), "=r"(r1), "=r"(r2), "=r"(r3) : "r"(addr));
}
__device__ __forceinline__ void mma16816(float* c, unsigned a0, unsigned a1, unsigned a2,
                                         unsigned a3, unsigned b0, unsigned b1) {
    asm volatile("mma.sync.aligned.m16n8k16.row.col.f32.bf16.bf16.f32 "
                 "{%0,%1,%2,%3}, {%4,%5,%6,%7}, {%8,%9}, {%0,%1,%2,%3};"
                 : "+f"(c[0]), "+f"(c[1]), "+f"(c[2]), "+f"(c[3])
                 : "r"(a0), "r"(a1), "r"(a2), "r"(a3), "r"(b0), "r"(b1));
}

// ---------------- fused flash attention (R6, best-measured) ----------------
// 8 warps x 16 query rows = 128-row tile; FBC=64 keys/iter, double-buffered.
// K via NON-TRANS ldmatrix (B-frag dual of row-major K tile); V via trans.
// No max subtraction (|S| < ~1); l partial sums per-lane, reduced at end.
#define FD   256
#define FBR  128
#define FBC  64
#define FLDQ 264            // halves; 528B pitch (33x16B) -> ldmatrix-aligned
#define FNIT (N_ / FBC)     // 64
#define FSMEM (3 * 128 * FLDQ * 2)

__global__ void __launch_bounds__(256, 1)
flash_attn(const __nv_bfloat16* __restrict__ Qg,
           const __nv_bfloat16* __restrict__ Kg,
           const __nv_bfloat16* __restrict__ Vg,
           __nv_bfloat16* __restrict__ Hg) {
    extern __shared__ __align__(128) unsigned char smem[];
    __nv_bfloat16* Qs = (__nv_bfloat16*)smem;          // 128*264 halves
    __nv_bfloat16* Ks = Qs + FBR * FLDQ;               // 2 bufs x 64*264
    __nv_bfloat16* Vs = Ks + 2 * FBC * FLDQ;           // 2 bufs x 64*264

    const int tid  = threadIdx.x;
    const int w    = tid >> 5;
    const int lane = tid & 31;
    const int n0   = blockIdx.x * FBR;
    const int b    = blockIdx.y;

    const __nv_bfloat16* Qp = Qg + ((size_t)b * N_ + n0) * FD;
    const __nv_bfloat16* Kp = Kg + (size_t)b * N_ * FD;
    const __nv_bfloat16* Vp = Vg + (size_t)b * N_ * FD;

    // Q tile -> smem
    #pragma unroll
    for (int t = 0; t < 16; t++) {
        int id = tid + t * 256;
        int r = id >> 5, c = id & 31;
        *(uint4*)(Qs + r * FLDQ + c * 8) = *(const uint4*)(Qp + (size_t)r * FD + c * 8);
    }

    const unsigned qbase = smem_u32(Qs + (w * 16 + (lane & 15)) * FLDQ + ((lane >> 4) << 3));
    const unsigned kbase = smem_u32(Ks + (lane & 7) * FLDQ + ((lane >> 3) << 3));
    const unsigned vbase = smem_u32(Vs + (lane & 15) * FLDQ + ((lane >> 4) << 3));
    const unsigned bufstep = FBC * FLDQ * 2;  // bytes per K/V buffer

    float oacc[32][4];
    #pragma unroll
    for (int t = 0; t < 32; t++)
        #pragma unroll
        for (int i = 0; i < 4; i++) oacc[t][i] = 0.f;
    float l0 = 0.f, l1 = 0.f;

    auto loadKV = [&](int j, int buf) {
        const __nv_bfloat16* kp = Kp + (size_t)j * FBC * FD;
        const __nv_bfloat16* vp = Vp + (size_t)j * FBC * FD;
        __nv_bfloat16* kd = Ks + buf * FBC * FLDQ;
        __nv_bfloat16* vd = Vs + buf * FBC * FLDQ;
        #pragma unroll
        for (int t = 0; t < 8; t++) {
            int id = tid + t * 256;         // 0..2047 = 64 rows x 32 chunks
            int r = id >> 5, c = id & 31;
            cp_async16(kd + r * FLDQ + c * 8, kp + (size_t)r * FD + c * 8);
            cp_async16(vd + r * FLDQ + c * 8, vp + (size_t)r * FD + c * 8);
        }
        cp_commit();
    };

    loadKV(0, 0);

    for (int j = 0; j < FNIT; j++) {
        asm volatile("cp.async.wait_group 0;\n" ::: "memory");
        __syncthreads();
        if (j + 1 < FNIT) loadKV(j + 1, (j + 1) & 1);

        const unsigned kb = kbase + (unsigned)(j & 1) * bufstep;
        const unsigned vb = vbase + (unsigned)(j & 1) * bufstep;

        // ---- S = Q @ K^T : 8 n8-tiles (64 keys), k=256 ----
        float sacc[8][4];
        #pragma unroll
        for (int t = 0; t < 8; t++)
            #pragma unroll
            for (int i = 0; i < 4; i++) sacc[t][i] = 0.f;

        #pragma unroll
        for (int kk2 = 0; kk2 < 8; kk2++) {          // two k16 steps per pass
            unsigned qa0, qa1, qa2, qa3, qc0, qc1, qc2, qc3;
            ldsm4(qbase + (unsigned)(2 * kk2) * 32u, qa0, qa1, qa2, qa3);
            ldsm4(qbase + (unsigned)(2 * kk2 + 1) * 32u, qc0, qc1, qc2, qc3);
            #pragma unroll
            for (int jt = 0; jt < 8; jt++) {
                unsigned b0, b1, b2, b3;
                ldsm4(kb + (unsigned)jt * (8u * FLDQ * 2u) + (unsigned)kk2 * 64u,
                      b0, b1, b2, b3);
                mma16816(sacc[jt], qa0, qa1, qa2, qa3, b0, b1);
                mma16816(sacc[jt], qc0, qc1, qc2, qc3, b2, b3);
            }
        }

        // ---- exp in registers, per-lane partial sums, pack P A-fragments ----
        unsigned pa[4][4];
        #pragma unroll
        for (int kk = 0; kk < 4; kk++) {
            #pragma unroll
            for (int tt = 0; tt < 2; tt++) {
                int jt = 2 * kk + tt;
                float e0 = __expf(sacc[jt][0]);
                float e1 = __expf(sacc[jt][1]);
                float e2 = __expf(sacc[jt][2]);
                float e3 = __expf(sacc[jt][3]);
                l0 += e0 + e1;
                l1 += e2 + e3;
                pa[kk][tt * 2 + 0] = pack_bf16(e0, e1);
                pa[kk][tt * 2 + 1] = pack_bf16(e2, e3);
            }
        }

        // ---- O += P @ V : 64 keys (4 k16 steps) x 256 cols (32 n8 tiles) ----
        #pragma unroll
        for (int kk = 0; kk < 4; kk++) {
            #pragma unroll
            for (int jt = 0; jt < 16; jt++) {
                unsigned v0, v1, v2, v3;
                ldsm4t(vb + (unsigned)kk * (16u * FLDQ * 2u) + (unsigned)jt * 32u,
                       v0, v1, v2, v3);
                mma16816(oacc[2 * jt],     pa[kk][0], pa[kk][1], pa[kk][2], pa[kk][3], v0, v1);
                mma16816(oacc[2 * jt + 1], pa[kk][0], pa[kk][1], pa[kk][2], pa[kk][3], v2, v3);
            }
        }
    }

    // ---- final l reduction over the 4 lanes sharing a row ----
    l0 += __shfl_xor_sync(0xffffffffu, l0, 1);
    l0 += __shfl_xor_sync(0xffffffffu, l0, 2);
    l1 += __shfl_xor_sync(0xffffffffu, l1, 1);
    l1 += __shfl_xor_sync(0xffffffffu, l1, 2);
    float inv0 = 1.f / l0;
    float inv1 = 1.f / l1;

    int gr0 = n0 + w * 16 + (lane >> 2);
    int gr1 = gr0 + 8;
    int cb  = 2 * (lane & 3);
    __nv_bfloat16* Hp = Hg + (size_t)b * N_ * C_;
    #pragma unroll
    for (int t = 0; t < 32; t++) {
        int col = t * 8 + cb;
        *(unsigned*)&Hp[(size_t)gr0 * C_ + col] = pack_bf16(oacc[t][0] * inv0, oacc[t][1] * inv0);
        *(unsigned*)&Hp[(size_t)gr1 * C_ + col] = pack_bf16(oacc[t][2] * inv1, oacc[t][3] * inv1);
    }
}

// ---------------- launch ----------------
extern "C" void kernel_launch(void* const* d_in, const int* in_sizes, int n_in,
                              void* d_out, int out_size) {
    const float* x   = (const float*)d_in[0];
    const float* gsc = (const float*)d_in[1];
    const float* gbi = (const float*)d_in[2];
    const float* wq  = (const float*)d_in[3];
    const float* bq  = (const float*)d_in[4];
    const float* wk  = (const float*)d_in[5];
    const float* bk  = (const float*)d_in[6];
    const float* wv  = (const float*)d_in[7];
    const float* bv  = (const float*)d_in[8];
    const float* wp  = (const float*)d_in[9];
    const float* bp  = (const float*)d_in[10];

    void *p_hn, *p_Q, *p_K, *p_V, *p_H, *p_wqkv, *p_wp;
    cudaGetSymbolAddress(&p_hn, g_hn);
    cudaGetSymbolAddress(&p_Q, g_Q);
    cudaGetSymbolAddress(&p_K, g_K);
    cudaGetSymbolAddress(&p_V, g_V);
    cudaGetSymbolAddress(&p_H, g_H);
    cudaGetSymbolAddress(&p_wqkv, g_wqkv);
    cudaGetSymbolAddress(&p_wp, g_wp);

    static int smem_set = 0;
    if (!smem_set) {
        cudaFuncSetAttribute(flash_attn, cudaFuncAttributeMaxDynamicSharedMemorySize, FSMEM);
        cudaFuncSetAttribute(groupnorm_kernel, cudaFuncAttributeMaxDynamicSharedMemorySize,
                             8 * N_ * 4);
        cudaFuncSetAttribute(gemm_qkv, cudaFuncAttributeMaxDynamicSharedMemorySize, GSMEM);
        cudaFuncSetAttribute(gemm_proj, cudaFuncAttributeMaxDynamicSharedMemorySize, GSMEM);
        smem_set = 1;
    }

    convert_weights<<<(C_ * C_ + 255) / 256, 256>>>(wq, wk, wv, wp);
    groupnorm_kernel<<<B_ * GROUPS_, 256, 8 * N_ * 4>>>(x, gsc, gbi);

    // fused QKV: one pipelined GEMM over packed [768,256] weights (Q folds 1/16)
    dim3 gqkv((B_ * N_) / BM, (3 * C_) / BN);
    gemm_qkv<<<gqkv, 256, GSMEM>>>(
        (const __nv_bfloat16*)p_hn, (const __nv_bfloat16*)p_wqkv,
        (__nv_bfloat16*)p_Q, (__nv_bfloat16*)p_K, (__nv_bfloat16*)p_V, bq, bk, bv);

    // fused attention -> H bf16 directly
    dim3 gflash(N_ / FBR, B_);
    flash_attn<<<gflash, 256, FSMEM>>>(
        (const __nv_bfloat16*)p_Q, (const __nv_bfloat16*)p_K, (const __nv_bfloat16*)p_V,
        (__nv_bfloat16*)p_H);

    // out[b,o,n] = x + Wproj @ H^T + bproj  (fp32, direct to d_out)
    dim3 gpr(C_ / BM, N_ / BN, B_);
    gemm_proj<<<gpr, 256, GSMEM>>>(
        (const __nv_bfloat16*)p_wp, (const __nv_bfloat16*)p_H, (float*)d_out, bp, x);
}

// round 14
// speedup vs baseline: 1.5319x; 1.5319x over previous
#include <cuda_runtime.h>
#include <cuda_bf16.h>
#include <mma.h>

using namespace nvcuda;

#define B_ 8
#define C_ 256
#define N_ 4096
#define GROUPS_ 32

// ---------------- scratch (device globals; allocation-free) ----------------
static __device__ __nv_bfloat16 g_hn[(size_t)B_ * N_ * C_];   // 16 MB
static __device__ __nv_bfloat16 g_Q [(size_t)B_ * N_ * C_];
static __device__ __nv_bfloat16 g_K [(size_t)B_ * N_ * C_];
static __device__ __nv_bfloat16 g_V [(size_t)B_ * N_ * C_];
static __device__ __nv_bfloat16 g_H [(size_t)B_ * N_ * C_];
static __device__ __nv_bfloat16 g_wqkv[3 * C_ * C_];
static __device__ __nv_bfloat16 g_wp[C_ * C_];

// ---------------- generic helpers ----------------
__device__ __forceinline__ unsigned smem_u32(const void* p) {
    return (unsigned)__cvta_generic_to_shared(p);
}
__device__ __forceinline__ void cp_async16(void* sdst, const void* gsrc) {
    unsigned sa = smem_u32(sdst);
    asm volatile("cp.async.cg.shared.global [%0], [%1], 16;\n" :: "r"(sa), "l"(gsrc) : "memory");
}
__device__ __forceinline__ void cp_commit() {
    asm volatile("cp.async.commit_group;\n" ::: "memory");
}
__device__ __forceinline__ unsigned pack_bf16(float lo, float hi) {
    unsigned r;
    asm("cvt.rn.bf16x2.f32 %0, %1, %2;" : "=r"(r) : "f"(hi), "f"(lo));
    return r;
}

// ---------------- weight conversion fp32 -> bf16 ----------------
__global__ void convert_weights(const float* __restrict__ wq, const float* __restrict__ wk,
                                const float* __restrict__ wv, const float* __restrict__ wp) {
    int i = blockIdx.x * blockDim.x + threadIdx.x;
    if (i < C_ * C_) {
        g_wqkv[i]               = __float2bfloat16(wq[i]);
        g_wqkv[C_ * C_ + i]     = __float2bfloat16(wk[i]);
        g_wqkv[2 * C_ * C_ + i] = __float2bfloat16(wv[i]);
        g_wp[i]                 = __float2bfloat16(wp[i]);
    }
}

// ---------------- GroupNorm: x[b,c,n] -> hn[b,n,c] (bf16), single DRAM pass --
__global__ void groupnorm_kernel(const float* __restrict__ x,
                                 const float* __restrict__ gamma,
                                 const float* __restrict__ beta) {
    extern __shared__ float xs[];            // 8 * 4096 fp32 = 128 KB
    int bid = blockIdx.x;
    int b = bid >> 5;
    int g = bid & 31;
    const int ELEMS = 8 * N_;                // 32768
    const float* xg = x + ((size_t)(b * C_ + g * 8)) * N_;

    float s = 0.f, s2 = 0.f;
    for (int i = threadIdx.x; i < ELEMS; i += blockDim.x) {
        float v = xg[i];
        xs[i] = v;
        s += v; s2 += v * v;
    }
    __shared__ float sh[64];
    #pragma unroll
    for (int o = 16; o; o >>= 1) {
        s  += __shfl_xor_sync(0xffffffffu, s,  o);
        s2 += __shfl_xor_sync(0xffffffffu, s2, o);
    }
    int w = threadIdx.x >> 5, l = threadIdx.x & 31;
    if (l == 0) { sh[w] = s; sh[32 + w] = s2; }
    __syncthreads();
    if (threadIdx.x < 32) {
        float a = (l < 8) ? sh[l] : 0.f;
        float c = (l < 8) ? sh[32 + l] : 0.f;
        #pragma unroll
        for (int o = 4; o; o >>= 1) {
            a += __shfl_xor_sync(0xffffffffu, a, o);
            c += __shfl_xor_sync(0xffffffffu, c, o);
        }
        if (l == 0) { sh[0] = a; sh[1] = c; }
    }
    __syncthreads();
    float mean = sh[0] * (1.f / ELEMS);
    float var  = sh[1] * (1.f / ELEMS) - mean * mean;
    float rstd = rsqrtf(var + 1e-6f);

    float gm[8], bt[8];
    #pragma unroll
    for (int cl = 0; cl < 8; cl++) { gm[cl] = gamma[g * 8 + cl]; bt[cl] = beta[g * 8 + cl]; }

    __nv_bfloat16* outb = g_hn + (size_t)b * N_ * C_ + g * 8;
    for (int n = threadIdx.x; n < N_; n += blockDim.x) {
        __nv_bfloat16 tmp[8];
        #pragma unroll
        for (int cl = 0; cl < 8; cl++) {
            float v = (xs[cl * N_ + n] - mean) * rstd * gm[cl] + bt[cl];
            tmp[cl] = __float2bfloat16(v);
        }
        *(uint4*)(outb + (size_t)n * C_) = *(uint4*)tmp;
    }
}

// ---------------- 3-stage pipelined WMMA GEMM tiles ----------------
#define BM 128
#define BN 64
#define BK 32
#define LDA_S  (BK + 8)     // 40 halves
#define LDB_S  (BK + 8)
#define LDC_S  (BN + 4)     // 68 floats
#define STAGE_A (BM * LDA_S)            // halves
#define STAGE_B (BN * LDB_S)
#define STAGE_H (STAGE_A + STAGE_B)     // 12800 halves = 25600 B
#define NK (C_ / BK)                    // 8
#define GSMEM (3 * STAGE_H * 2)

#define GEMM_MMA_STAGE(AsP, BsP)                                               \
    do {                                                                       \
        _Pragma("unroll")                                                      \
        for (int ks = 0; ks < 2; ks++) {                                       \
            wmma::fragment<wmma::matrix_a, 16, 16, 16, __nv_bfloat16,          \
                           wmma::row_major> fa[2];                             \
            wmma::fragment<wmma::matrix_b, 16, 16, 16, __nv_bfloat16,          \
                           wmma::col_major> fb[2];                             \
            _Pragma("unroll")                                                  \
            for (int i = 0; i < 2; i++)                                        \
                wmma::load_matrix_sync(fa[i],                                  \
                    (AsP) + (wm * 32 + i * 16) * LDA_S + ks * 16, LDA_S);      \
            _Pragma("unroll")                                                  \
            for (int jj = 0; jj < 2; jj++)                                     \
                wmma::load_matrix_sync(fb[jj],                                 \
                    (BsP) + (wn * 32 + jj * 16) * LDB_S + ks * 16, LDB_S);     \
            _Pragma("unroll")                                                  \
            for (int i = 0; i < 2; i++)                                        \
                _Pragma("unroll")                                              \
                for (int jj = 0; jj < 2; jj++)                                 \
                    wmma::mma_sync(fc[i][jj], fa[i], fb[jj], fc[i][jj]);       \
        }                                                                      \
    } while (0)

// --- fused QKV: C[32768,768] = hn[32768,256] x Wqkv[768,256]^T, routed out ---
__global__ void __launch_bounds__(256)
gemm_qkv(const __nv_bfloat16* __restrict__ Abase,
         const __nv_bfloat16* __restrict__ Bbase,
         __nv_bfloat16* __restrict__ Qo, __nv_bfloat16* __restrict__ Ko,
         __nv_bfloat16* __restrict__ Vo,
         const float* __restrict__ bq, const float* __restrict__ bk,
         const float* __restrict__ bv) {
    extern __shared__ __align__(16) unsigned char smem[];
    __nv_bfloat16* Sh = (__nv_bfloat16*)smem;
    float* Csh = (float*)smem;

    int m0 = blockIdx.x * BM;
    int n0 = blockIdx.y * BN;
    int tid = threadIdx.x;
    int wid = tid >> 5;
    int wm = wid & 3, wn = wid >> 2;

    auto loadstage = [&](int ks) {
        __nv_bfloat16* As = Sh + (ks % 3) * STAGE_H;
        __nv_bfloat16* Bs = As + STAGE_A;
        int k0 = ks * BK;
        #pragma unroll
        for (int v = 0; v < 2; v++) {
            int idx = tid + v * 256;
            int r = idx >> 2, kv = idx & 3;
            cp_async16(As + r * LDA_S + kv * 8,
                       Abase + (size_t)(m0 + r) * C_ + k0 + kv * 8);
        }
        {
            int r = tid >> 2, kv = tid & 3;
            cp_async16(Bs + r * LDB_S + kv * 8,
                       Bbase + (size_t)(n0 + r) * C_ + k0 + kv * 8);
        }
        cp_commit();
    };

    wmma::fragment<wmma::accumulator, 16, 16, 16, float> fc[2][2];
    #pragma unroll
    for (int i = 0; i < 2; i++)
        #pragma unroll
        for (int j = 0; j < 2; j++) wmma::fill_fragment(fc[i][j], 0.f);

    loadstage(0);
    loadstage(1);
    for (int it = 0; it < NK; it++) {
        if (it < NK - 1) asm volatile("cp.async.wait_group 1;\n" ::: "memory");
        else             asm volatile("cp.async.wait_group 0;\n" ::: "memory");
        __syncthreads();
        __nv_bfloat16* As = Sh + (it % 3) * STAGE_H;
        __nv_bfloat16* Bs = As + STAGE_A;
        GEMM_MMA_STAGE(As, Bs);
        if (it + 2 < NK) loadstage(it + 2);
    }
    __syncthreads();

    #pragma unroll
    for (int i = 0; i < 2; i++)
        #pragma unroll
        for (int j = 0; j < 2; j++)
            wmma::store_matrix_sync(Csh + (wm * 32 + i * 16) * LDC_S + wn * 32 + j * 16,
                                    fc[i][j], LDC_S, wmma::mem_row_major);
    __syncthreads();

    int t = n0 >> 8;
    int o0 = n0 & 255;
    const float* bb = (t == 0) ? bq : (t == 1) ? bk : bv;
    float sc = (t == 0) ? 0.0625f : 1.f;
    __nv_bfloat16* dst = (t == 0) ? Qo : (t == 1) ? Ko : Vo;

    #pragma unroll
    for (int it = 0; it < (BM * BN) / 256; it++) {
        int v = tid + it * 256;
        int r = v >> 6, c = v & 63;
        float acc = Csh[r * LDC_S + c];
        dst[(size_t)(m0 + r) * C_ + o0 + c] = __float2bfloat16((acc + bb[o0 + c]) * sc);
    }
}

// --- proj: out[b,o,n] = x + Wp[256,256] @ H[b, n, :]^T + bias[o] ---
__global__ void __launch_bounds__(256)
gemm_proj(const __nv_bfloat16* __restrict__ Abase,   // Wp [256,256]
          const __nv_bfloat16* __restrict__ Bbase,   // H  [b][4096,256]
          float* __restrict__ Obase,
          const float* __restrict__ bias,
          const float* __restrict__ Xres) {
    extern __shared__ __align__(16) unsigned char smem[];
    __nv_bfloat16* Sh = (__nv_bfloat16*)smem;
    float* Csh = (float*)smem;

    int bz = blockIdx.z;
    const __nv_bfloat16* Bm = Bbase + (size_t)bz * N_ * C_;
    int m0 = blockIdx.x * BM;
    int n0 = blockIdx.y * BN;
    int tid = threadIdx.x;
    int wid = tid >> 5;
    int wm = wid & 3, wn = wid >> 2;

    auto loadstage = [&](int ks) {
        __nv_bfloat16* As = Sh + (ks % 3) * STAGE_H;
        __nv_bfloat16* Bs = As + STAGE_A;
        int k0 = ks * BK;
        #pragma unroll
        for (int v = 0; v < 2; v++) {
            int idx = tid + v * 256;
            int r = idx >> 2, kv = idx & 3;
            cp_async16(As + r * LDA_S + kv * 8,
                       Abase + (size_t)(m0 + r) * C_ + k0 + kv * 8);
        }
        {
            int r = tid >> 2, kv = tid & 3;
            cp_async16(Bs + r * LDB_S + kv * 8,
                       Bm + (size_t)(n0 + r) * C_ + k0 + kv * 8);
        }
        cp_commit();
    };

    wmma::fragment<wmma::accumulator, 16, 16, 16, float> fc[2][2];
    #pragma unroll
    for (int i = 0; i < 2; i++)
        #pragma unroll
        for (int j = 0; j < 2; j++) wmma::fill_fragment(fc[i][j], 0.f);

    loadstage(0);
    loadstage(1);
    for (int it = 0; it < NK; it++) {
        if (it < NK - 1) asm volatile("cp.async.wait_group 1;\n" ::: "memory");
        else             asm volatile("cp.async.wait_group 0;\n" ::: "memory");
        __syncthreads();
        __nv_bfloat16* As = Sh + (it % 3) * STAGE_H;
        __nv_bfloat16* Bs = As + STAGE_A;
        GEMM_MMA_STAGE(As, Bs);
        if (it + 2 < NK) loadstage(it + 2);
    }
    __syncthreads();

    #pragma unroll
    for (int i = 0; i < 2; i++)
        #pragma unroll
        for (int j = 0; j < 2; j++)
            wmma::store_matrix_sync(Csh + (wm * 32 + i * 16) * LDC_S + wn * 32 + j * 16,
                                    fc[i][j], LDC_S, wmma::mem_row_major);
    __syncthreads();

    float* O = Obase + (size_t)bz * C_ * N_;
    const float* X = Xres + (size_t)bz * C_ * N_;
    #pragma unroll
    for (int it = 0; it < (BM * BN) / 256; it++) {
        int v = tid + it * 256;
        int r = v >> 6, c = v & 63;
        float acc = Csh[r * LDC_S + c];
        int gr = m0 + r, gc = n0 + c;
        O[(size_t)gr * N_ + gc] = X[(size_t)gr * N_ + gc] + acc + bias[gr];
    }
}

// ---------------- flash PTX helpers ----------------
__device__ __forceinline__ void ldsm4(unsigned addr, unsigned& r0, unsigned& r1,
                                      unsigned& r2, unsigned& r3) {
    asm volatile("ldmatrix.sync.aligned.m8n8.x4.shared.b16 {%0,%1,%2,%3}, [%4];"
                 : "=r"(r0), "=r"(r1), "=r"(r2), "=r"(r3) : "r"(addr));
}
__device__ __forceinline__ void ldsm4t(unsigned addr, unsigned& r0, unsigned& r1,
                                       unsigned& r2, unsigned& r3) {
    asm volatile("ldmatrix.sync.aligned.m8n8.x4.trans.shared.b16 {%0,%1,%2,%3}, [%4];"
                 : "=r"(r0), "=r"(r1), "=r"(r2), "=r"(r3) : "r"(addr));
}
__device__ __forceinline__ void mma16816(float* c, unsigned a0, unsigned a1, unsigned a2,
                                         unsigned a3, unsigned b0, unsigned b1) {
    asm volatile("mma.sync.aligned.m16n8k16.row.col.f32.bf16.bf16.f32 "
                 "{%0,%1,%2,%3}, {%4,%5,%6,%7}, {%8,%9}, {%0,%1,%2,%3};"
                 : "+f"(c[0]), "+f"(c[1]), "+f"(c[2]), "+f"(c[3])
                 : "r"(a0), "r"(a1), "r"(a2), "r"(a3), "r"(b0), "r"(b1));
}

// ---------------- fused flash attention (R6 math + operand prefetch) -------
// 8 warps x 16 query rows = 128-row tile; FBC=64 keys/iter, double-buffered.
// K via NON-TRANS ldmatrix; V via trans. No max subtraction (|S| < ~1).
// Inner loops double-buffer the B-operand fragments (depth-1 prefetch) so the
// ldsm->MMA latency (29+ cyc) is covered by the previous group's MMAs.
#define FD   256
#define FBR  128
#define FBC  64
#define FLDQ 264            // halves; 528B pitch (33x16B) -> ldmatrix-aligned
#define FNIT (N_ / FBC)     // 64
#define FSMEM (3 * 128 * FLDQ * 2)

__global__ void __launch_bounds__(256, 1)
flash_attn(const __nv_bfloat16* __restrict__ Qg,
           const __nv_bfloat16* __restrict__ Kg,
           const __nv_bfloat16* __restrict__ Vg,
           __nv_bfloat16* __restrict__ Hg) {
    extern __shared__ __align__(128) unsigned char smem[];
    __nv_bfloat16* Qs = (__nv_bfloat16*)smem;          // 128*264 halves
    __nv_bfloat16* Ks = Qs + FBR * FLDQ;               // 2 bufs x 64*264
    __nv_bfloat16* Vs = Ks + 2 * FBC * FLDQ;           // 2 bufs x 64*264

    const int tid  = threadIdx.x;
    const int w    = tid >> 5;
    const int lane = tid & 31;
    const int n0   = blockIdx.x * FBR;
    const int b    = blockIdx.y;

    const __nv_bfloat16* Qp = Qg + ((size_t)b * N_ + n0) * FD;
    const __nv_bfloat16* Kp = Kg + (size_t)b * N_ * FD;
    const __nv_bfloat16* Vp = Vg + (size_t)b * N_ * FD;

    // Q tile -> smem
    #pragma unroll
    for (int t = 0; t < 16; t++) {
        int id = tid + t * 256;
        int r = id >> 5, c = id & 31;
        *(uint4*)(Qs + r * FLDQ + c * 8) = *(const uint4*)(Qp + (size_t)r * FD + c * 8);
    }

    const unsigned qbase = smem_u32(Qs + (w * 16 + (lane & 15)) * FLDQ + ((lane >> 4) << 3));
    const unsigned kbase = smem_u32(Ks + (lane & 7) * FLDQ + ((lane >> 3) << 3));
    const unsigned vbase = smem_u32(Vs + (lane & 15) * FLDQ + ((lane >> 4) << 3));
    const unsigned bufstep = FBC * FLDQ * 2;  // bytes per K/V buffer

    float oacc[32][4];
    #pragma unroll
    for (int t = 0; t < 32; t++)
        #pragma unroll
        for (int i = 0; i < 4; i++) oacc[t][i] = 0.f;
    float l0 = 0.f, l1 = 0.f;

    auto loadKV = [&](int j, int buf) {
        const __nv_bfloat16* kp = Kp + (size_t)j * FBC * FD;
        const __nv_bfloat16* vp = Vp + (size_t)j * FBC * FD;
        __nv_bfloat16* kd = Ks + buf * FBC * FLDQ;
        __nv_bfloat16* vd = Vs + buf * FBC * FLDQ;
        #pragma unroll
        for (int t = 0; t < 8; t++) {
            int id = tid + t * 256;         // 0..2047 = 64 rows x 32 chunks
            int r = id >> 5, c = id & 31;
            cp_async16(kd + r * FLDQ + c * 8, kp + (size_t)r * FD + c * 8);
            cp_async16(vd + r * FLDQ + c * 8, vp + (size_t)r * FD + c * 8);
        }
        cp_commit();
    };

    loadKV(0, 0);

    for (int j = 0; j < FNIT; j++) {
        asm volatile("cp.async.wait_group 0;\n" ::: "memory");
        __syncthreads();
        if (j + 1 < FNIT) loadKV(j + 1, (j + 1) & 1);

        const unsigned kb = kbase + (unsigned)(j & 1) * bufstep;
        const unsigned vb = vbase + (unsigned)(j & 1) * bufstep;

        // ---- S = Q @ K^T : 8 n8-tiles (64 keys), k=256, K-frag prefetch ----
        float sacc[8][4];
        #pragma unroll
        for (int t = 0; t < 8; t++)
            #pragma unroll
            for (int i = 0; i < 4; i++) sacc[t][i] = 0.f;

        {
            unsigned kf[2][4];
            ldsm4(kb, kf[0][0], kf[0][1], kf[0][2], kf[0][3]);   // (kk2=0, jt=0)
            #pragma unroll
            for (int kk2 = 0; kk2 < 8; kk2++) {
                unsigned qa0, qa1, qa2, qa3, qc0, qc1, qc2, qc3;
                ldsm4(qbase + (unsigned)(2 * kk2) * 32u, qa0, qa1, qa2, qa3);
                ldsm4(qbase + (unsigned)(2 * kk2 + 1) * 32u, qc0, qc1, qc2, qc3);
                #pragma unroll
                for (int jt = 0; jt < 8; jt++) {
                    int cur = (kk2 * 8 + jt) & 1;
                    int nxt = cur ^ 1;
                    // prefetch next fragment (next jt, or jt=0 of next kk2)
                    if (jt < 7) {
                        ldsm4(kb + (unsigned)(jt + 1) * (8u * FLDQ * 2u)
                                 + (unsigned)kk2 * 64u,
                              kf[nxt][0], kf[nxt][1], kf[nxt][2], kf[nxt][3]);
                    } else if (kk2 < 7) {
                        ldsm4(kb + (unsigned)(kk2 + 1) * 64u,
                              kf[nxt][0], kf[nxt][1], kf[nxt][2], kf[nxt][3]);
                    }
                    mma16816(sacc[jt], qa0, qa1, qa2, qa3, kf[cur][0], kf[cur][1]);
                    mma16816(sacc[jt], qc0, qc1, qc2, qc3, kf[cur][2], kf[cur][3]);
                }
            }
        }

        // ---- exp in registers, per-lane partial sums, pack P A-fragments ----
        unsigned pa[4][4];
        #pragma unroll
        for (int kk = 0; kk < 4; kk++) {
            #pragma unroll
            for (int tt = 0; tt < 2; tt++) {
                int jt = 2 * kk + tt;
                float e0 = __expf(sacc[jt][0]);
                float e1 = __expf(sacc[jt][1]);
                float e2 = __expf(sacc[jt][2]);
                float e3 = __expf(sacc[jt][3]);
                l0 += e0 + e1;
                l1 += e2 + e3;
                pa[kk][tt * 2 + 0] = pack_bf16(e0, e1);
                pa[kk][tt * 2 + 1] = pack_bf16(e2, e3);
            }
        }

        // ---- O += P @ V : 64 keys x 256 cols, V-frag prefetch ----
        {
            unsigned vf[2][4];
            ldsm4t(vb, vf[0][0], vf[0][1], vf[0][2], vf[0][3]);  // (kk=0, jt=0)
            #pragma unroll
            for (int kk = 0; kk < 4; kk++) {
                #pragma unroll
                for (int jt = 0; jt < 16; jt++) {
                    int cur = (kk * 16 + jt) & 1;
                    int nxt = cur ^ 1;
                    if (jt < 15) {
                        ldsm4t(vb + (unsigned)kk * (16u * FLDQ * 2u)
                                  + (unsigned)(jt + 1) * 32u,
                               vf[nxt][0], vf[nxt][1], vf[nxt][2], vf[nxt][3]);
                    } else if (kk < 3) {
                        ldsm4t(vb + (unsigned)(kk + 1) * (16u * FLDQ * 2u),
                               vf[nxt][0], vf[nxt][1], vf[nxt][2], vf[nxt][3]);
                    }
                    mma16816(oacc[2 * jt],     pa[kk][0], pa[kk][1], pa[kk][2], pa[kk][3],
                             vf[cur][0], vf[cur][1]);
                    mma16816(oacc[2 * jt + 1], pa[kk][0], pa[kk][1], pa[kk][2], pa[kk][3],
                             vf[cur][2], vf[cur][3]);
                }
            }
        }
    }

    // ---- final l reduction over the 4 lanes sharing a row ----
    l0 += __shfl_xor_sync(0xffffffffu, l0, 1);
    l0 += __shfl_xor_sync(0xffffffffu, l0, 2);
    l1 += __shfl_xor_sync(0xffffffffu, l1, 1);
    l1 += __shfl_xor_sync(0xffffffffu, l1, 2);
    float inv0 = 1.f / l0;
    float inv1 = 1.f / l1;

    int gr0 = n0 + w * 16 + (lane >> 2);
    int gr1 = gr0 + 8;
    int cb  = 2 * (lane & 3);
    __nv_bfloat16* Hp = Hg + (size_t)b * N_ * C_;
    #pragma unroll
    for (int t = 0; t < 32; t++) {
        int col = t * 8 + cb;
        *(unsigned*)&Hp[(size_t)gr0 * C_ + col] = pack_bf16(oacc[t][0] * inv0, oacc[t][1] * inv0);
        *(unsigned*)&Hp[(size_t)gr1 * C_ + col] = pack_bf16(oacc[t][2] * inv1, oacc[t][3] * inv1);
    }
}

// ---------------- launch ----------------
extern "C" void kernel_launch(void* const* d_in, const int* in_sizes, int n_in,
                              void* d_out, int out_size) {
    const float* x   = (const float*)d_in[0];
    const float* gsc = (const float*)d_in[1];
    const float* gbi = (const float*)d_in[2];
    const float* wq  = (const float*)d_in[3];
    const float* bq  = (const float*)d_in[4];
    const float* wk  = (const float*)d_in[5];
    const float* bk  = (const float*)d_in[6];
    const float* wv  = (const float*)d_in[7];
    const float* bv  = (const float*)d_in[8];
    const float* wp  = (const float*)d_in[9];
    const float* bp  = (const float*)d_in[10];

    void *p_hn, *p_Q, *p_K, *p_V, *p_H, *p_wqkv, *p_wp;
    cudaGetSymbolAddress(&p_hn, g_hn);
    cudaGetSymbolAddress(&p_Q, g_Q);
    cudaGetSymbolAddress(&p_K, g_K);
    cudaGetSymbolAddress(&p_V, g_V);
    cudaGetSymbolAddress(&p_H, g_H);
    cudaGetSymbolAddress(&p_wqkv, g_wqkv);
    cudaGetSymbolAddress(&p_wp, g_wp);

    static int smem_set = 0;
    if (!smem_set) {
        cudaFuncSetAttribute(flash_attn, cudaFuncAttributeMaxDynamicSharedMemorySize, FSMEM);
        cudaFuncSetAttribute(groupnorm_kernel, cudaFuncAttributeMaxDynamicSharedMemorySize,
                             8 * N_ * 4);
        cudaFuncSetAttribute(gemm_qkv, cudaFuncAttributeMaxDynamicSharedMemorySize, GSMEM);
        cudaFuncSetAttribute(gemm_proj, cudaFuncAttributeMaxDynamicSharedMemorySize, GSMEM);
        smem_set = 1;
    }

    convert_weights<<<(C_ * C_ + 255) / 256, 256>>>(wq, wk, wv, wp);
    groupnorm_kernel<<<B_ * GROUPS_, 256, 8 * N_ * 4>>>(x, gsc, gbi);

    // fused QKV: one pipelined GEMM over packed [768,256] weights (Q folds 1/16)
    dim3 gqkv((B_ * N_) / BM, (3 * C_) / BN);
    gemm_qkv<<<gqkv, 256, GSMEM>>>(
        (const __nv_bfloat16*)p_hn, (const __nv_bfloat16*)p_wqkv,
        (__nv_bfloat16*)p_Q, (__nv_bfloat16*)p_K, (__nv_bfloat16*)p_V, bq, bk, bv);

    // fused attention -> H bf16 directly
    dim3 gflash(N_ / FBR, B_);
    flash_attn<<<gflash, 256, FSMEM>>>(
        (const __nv_bfloat16*)p_Q, (const __nv_bfloat16*)p_K, (const __nv_bfloat16*)p_V,
        (__nv_bfloat16*)p_H);

    // out[b,o,n] = x + Wproj @ H^T + bproj  (fp32, direct to d_out)
    dim3 gpr(C_ / BM, N_ / BN, B_);
    gemm_proj<<<gpr, 256, GSMEM>>>(
        (const __nv_bfloat16*)p_wp, (const __nv_bfloat16*)p_H, (float*)d_out, bp, x);
}

// round 15
// speedup vs baseline: 1.6161x; 1.0549x over previous
#include <cuda_runtime.h>
#include <cuda_bf16.h>
#include <mma.h>

using namespace nvcuda;

#define B_ 8
#define C_ 256
#define N_ 4096
#define GROUPS_ 32

// ---------------- scratch (device globals; allocation-free) ----------------
static __device__ __nv_bfloat16 g_hn[(size_t)B_ * N_ * C_];   // 16 MB
static __device__ __nv_bfloat16 g_Q [(size_t)B_ * N_ * C_];
static __device__ __nv_bfloat16 g_K [(size_t)B_ * N_ * C_];
static __device__ __nv_bfloat16 g_V [(size_t)B_ * N_ * C_];
static __device__ __nv_bfloat16 g_H [(size_t)B_ * N_ * C_];
static __device__ __nv_bfloat16 g_wqkv[3 * C_ * C_];
static __device__ __nv_bfloat16 g_wp[C_ * C_];

// ---------------- generic helpers ----------------
__device__ __forceinline__ unsigned smem_u32(const void* p) {
    return (unsigned)__cvta_generic_to_shared(p);
}
__device__ __forceinline__ void cp_async16(void* sdst, const void* gsrc) {
    unsigned sa = smem_u32(sdst);
    asm volatile("cp.async.cg.shared.global [%0], [%1], 16;\n" :: "r"(sa), "l"(gsrc) : "memory");
}
__device__ __forceinline__ void cp_commit() {
    asm volatile("cp.async.commit_group;\n" ::: "memory");
}
__device__ __forceinline__ unsigned pack_bf16(float lo, float hi) {
    unsigned r;
    asm("cvt.rn.bf16x2.f32 %0, %1, %2;" : "=r"(r) : "f"(hi), "f"(lo));
    return r;
}

// ---------------- weight conversion fp32 -> bf16 ----------------
__global__ void convert_weights(const float* __restrict__ wq, const float* __restrict__ wk,
                                const float* __restrict__ wv, const float* __restrict__ wp) {
    int i = blockIdx.x * blockDim.x + threadIdx.x;
    if (i < C_ * C_) {
        g_wqkv[i]               = __float2bfloat16(wq[i]);
        g_wqkv[C_ * C_ + i]     = __float2bfloat16(wk[i]);
        g_wqkv[2 * C_ * C_ + i] = __float2bfloat16(wv[i]);
        g_wp[i]                 = __float2bfloat16(wp[i]);
    }
}

// ---------------- GroupNorm: x[b,c,n] -> hn[b,n,c] (bf16), 1024 thr, 1 pass --
__global__ void groupnorm_kernel(const float* __restrict__ x,
                                 const float* __restrict__ gamma,
                                 const float* __restrict__ beta) {
    extern __shared__ float xs[];            // 8 * 4096 fp32 = 128 KB
    int bid = blockIdx.x;
    int b = bid >> 5;
    int g = bid & 31;
    const int ELEMS = 8 * N_;                // 32768
    const float* xg = x + ((size_t)(b * C_ + g * 8)) * N_;

    float s = 0.f, s2 = 0.f;
    for (int i = threadIdx.x; i < ELEMS; i += blockDim.x) {
        float v = xg[i];
        xs[i] = v;
        s += v; s2 += v * v;
    }
    __shared__ float sh[64];
    #pragma unroll
    for (int o = 16; o; o >>= 1) {
        s  += __shfl_xor_sync(0xffffffffu, s,  o);
        s2 += __shfl_xor_sync(0xffffffffu, s2, o);
    }
    int w = threadIdx.x >> 5, l = threadIdx.x & 31;
    if (l == 0) { sh[w] = s; sh[32 + w] = s2; }
    __syncthreads();
    if (threadIdx.x < 32) {
        float a = sh[l];          // 32 warps
        float c = sh[32 + l];
        #pragma unroll
        for (int o = 16; o; o >>= 1) {
            a += __shfl_xor_sync(0xffffffffu, a, o);
            c += __shfl_xor_sync(0xffffffffu, c, o);
        }
        if (l == 0) { sh[0] = a; sh[1] = c; }
    }
    __syncthreads();
    float mean = sh[0] * (1.f / ELEMS);
    float var  = sh[1] * (1.f / ELEMS) - mean * mean;
    float rstd = rsqrtf(var + 1e-6f);

    float gm[8], bt[8];
    #pragma unroll
    for (int cl = 0; cl < 8; cl++) { gm[cl] = gamma[g * 8 + cl]; bt[cl] = beta[g * 8 + cl]; }

    __nv_bfloat16* outb = g_hn + (size_t)b * N_ * C_ + g * 8;
    for (int n = threadIdx.x; n < N_; n += blockDim.x) {
        __nv_bfloat16 tmp[8];
        #pragma unroll
        for (int cl = 0; cl < 8; cl++) {
            float v = (xs[cl * N_ + n] - mean) * rstd * gm[cl] + bt[cl];
            tmp[cl] = __float2bfloat16(v);
        }
        *(uint4*)(outb + (size_t)n * C_) = *(uint4*)tmp;
    }
}

// ---------------- 3-stage pipelined WMMA GEMM, 128x128 tiles ----------------
#define BM 128
#define BN 128
#define BK 32
#define LDA_S  (BK + 8)     // 40 halves
#define LDB_S  (BK + 8)
#define LDC_S  (BN + 4)     // 132 floats
#define STAGE_A (BM * LDA_S)            // 5120 halves
#define STAGE_B (BN * LDB_S)            // 5120 halves
#define STAGE_H (STAGE_A + STAGE_B)     // 10240 halves = 20480 B
#define NK (C_ / BK)                    // 8
#define GSMEM (BM * LDC_S * 4)          // epilogue 67584 B > 3*stage 61440 B

// 8 warps: wm = wid&3 (row group of 32), wn = wid>>2 (col group of 64)
#define GEMM_MMA_STAGE(AsP, BsP)                                               \
    do {                                                                       \
        _Pragma("unroll")                                                      \
        for (int ks = 0; ks < 2; ks++) {                                       \
            wmma::fragment<wmma::matrix_a, 16, 16, 16, __nv_bfloat16,          \
                           wmma::row_major> fa[2];                             \
            wmma::fragment<wmma::matrix_b, 16, 16, 16, __nv_bfloat16,          \
                           wmma::col_major> fb[4];                             \
            _Pragma("unroll")                                                  \
            for (int i = 0; i < 2; i++)                                        \
                wmma::load_matrix_sync(fa[i],                                  \
                    (AsP) + (wm * 32 + i * 16) * LDA_S + ks * 16, LDA_S);      \
            _Pragma("unroll")                                                  \
            for (int jj = 0; jj < 4; jj++)                                     \
                wmma::load_matrix_sync(fb[jj],                                 \
                    (BsP) + (wn * 64 + jj * 16) * LDB_S + ks * 16, LDB_S);     \
            _Pragma("unroll")                                                  \
            for (int i = 0; i < 2; i++)                                        \
                _Pragma("unroll")                                              \
                for (int jj = 0; jj < 4; jj++)                                 \
                    wmma::mma_sync(fc[i][jj], fa[i], fb[jj], fc[i][jj]);       \
        }                                                                      \
    } while (0)

#define GEMM_LOADSTAGE(Aptr, Bptr, ks)                                         \
    do {                                                                       \
        __nv_bfloat16* As = Sh + ((ks) % 3) * STAGE_H;                         \
        __nv_bfloat16* Bs = As + STAGE_A;                                      \
        int k0 = (ks) * BK;                                                    \
        _Pragma("unroll")                                                      \
        for (int v = 0; v < 2; v++) {                                          \
            int idx = tid + v * 256;                                           \
            int r = idx >> 2, kv = idx & 3;                                    \
            cp_async16(As + r * LDA_S + kv * 8,                                \
                       (Aptr) + (size_t)(m0 + r) * C_ + k0 + kv * 8);          \
        }                                                                      \
        _Pragma("unroll")                                                      \
        for (int v = 0; v < 2; v++) {                                          \
            int idx = tid + v * 256;                                           \
            int r = idx >> 2, kv = idx & 3;                                    \
            cp_async16(Bs + r * LDB_S + kv * 8,                                \
                       (Bptr) + (size_t)(n0 + r) * C_ + k0 + kv * 8);          \
        }                                                                      \
        cp_commit();                                                           \
    } while (0)

// --- fused QKV: C[32768,768] = hn[32768,256] x Wqkv[768,256]^T, routed out ---
__global__ void __launch_bounds__(256)
gemm_qkv(const __nv_bfloat16* __restrict__ Abase,
         const __nv_bfloat16* __restrict__ Bbase,
         __nv_bfloat16* __restrict__ Qo, __nv_bfloat16* __restrict__ Ko,
         __nv_bfloat16* __restrict__ Vo,
         const float* __restrict__ bq, const float* __restrict__ bk,
         const float* __restrict__ bv) {
    extern __shared__ __align__(16) unsigned char smem[];
    __nv_bfloat16* Sh = (__nv_bfloat16*)smem;
    float* Csh = (float*)smem;

    int m0 = blockIdx.x * BM;
    int n0 = blockIdx.y * BN;
    int tid = threadIdx.x;
    int wid = tid >> 5;
    int wm = wid & 3, wn = wid >> 2;

    wmma::fragment<wmma::accumulator, 16, 16, 16, float> fc[2][4];
    #pragma unroll
    for (int i = 0; i < 2; i++)
        #pragma unroll
        for (int j = 0; j < 4; j++) wmma::fill_fragment(fc[i][j], 0.f);

    GEMM_LOADSTAGE(Abase, Bbase, 0);
    GEMM_LOADSTAGE(Abase, Bbase, 1);
    for (int it = 0; it < NK; it++) {
        if (it < NK - 1) asm volatile("cp.async.wait_group 1;\n" ::: "memory");
        else             asm volatile("cp.async.wait_group 0;\n" ::: "memory");
        __syncthreads();
        __nv_bfloat16* As = Sh + (it % 3) * STAGE_H;
        __nv_bfloat16* Bs = As + STAGE_A;
        GEMM_MMA_STAGE(As, Bs);
        if (it + 2 < NK) GEMM_LOADSTAGE(Abase, Bbase, it + 2);
    }
    __syncthreads();

    #pragma unroll
    for (int i = 0; i < 2; i++)
        #pragma unroll
        for (int j = 0; j < 4; j++)
            wmma::store_matrix_sync(Csh + (wm * 32 + i * 16) * LDC_S + wn * 64 + j * 16,
                                    fc[i][j], LDC_S, wmma::mem_row_major);
    __syncthreads();

    // routing: 128-wide tile lies wholly inside one of Q/K/V (256-col blocks)
    int t = n0 >> 8;
    int o0 = n0 & 255;
    const float* bb = (t == 0) ? bq : (t == 1) ? bk : bv;
    float sc = (t == 0) ? 0.0625f : 1.f;
    __nv_bfloat16* dst = (t == 0) ? Qo : (t == 1) ? Ko : Vo;

    #pragma unroll
    for (int it = 0; it < 32; it++) {
        int v = tid + it * 256;            // pair index 0..8191
        int r = v >> 6, c2 = (v & 63) * 2;
        float a0 = Csh[r * LDC_S + c2];
        float a1 = Csh[r * LDC_S + c2 + 1];
        unsigned pk = pack_bf16((a0 + bb[o0 + c2]) * sc, (a1 + bb[o0 + c2 + 1]) * sc);
        *(unsigned*)(dst + (size_t)(m0 + r) * C_ + o0 + c2) = pk;
    }
}

// --- proj: out[b,o,n] = x + Wp[256,256] @ H[b, n, :]^T + bias[o] ---
__global__ void __launch_bounds__(256)
gemm_proj(const __nv_bfloat16* __restrict__ Abase,   // Wp [256,256]
          const __nv_bfloat16* __restrict__ Bbase,   // H  [b][4096,256]
          float* __restrict__ Obase,
          const float* __restrict__ bias,
          const float* __restrict__ Xres) {
    extern __shared__ __align__(16) unsigned char smem[];
    __nv_bfloat16* Sh = (__nv_bfloat16*)smem;
    float* Csh = (float*)smem;

    int bz = blockIdx.z;
    const __nv_bfloat16* Bm = Bbase + (size_t)bz * N_ * C_;
    int m0 = blockIdx.x * BM;
    int n0 = blockIdx.y * BN;
    int tid = threadIdx.x;
    int wid = tid >> 5;
    int wm = wid & 3, wn = wid >> 2;

    wmma::fragment<wmma::accumulator, 16, 16, 16, float> fc[2][4];
    #pragma unroll
    for (int i = 0; i < 2; i++)
        #pragma unroll
        for (int j = 0; j < 4; j++) wmma::fill_fragment(fc[i][j], 0.f);

    GEMM_LOADSTAGE(Abase, Bm, 0);
    GEMM_LOADSTAGE(Abase, Bm, 1);
    for (int it = 0; it < NK; it++) {
        if (it < NK - 1) asm volatile("cp.async.wait_group 1;\n" ::: "memory");
        else             asm volatile("cp.async.wait_group 0;\n" ::: "memory");
        __syncthreads();
        __nv_bfloat16* As = Sh + (it % 3) * STAGE_H;
        __nv_bfloat16* Bs = As + STAGE_A;
        GEMM_MMA_STAGE(As, Bs);
        if (it + 2 < NK) GEMM_LOADSTAGE(Abase, Bm, it + 2);
    }
    __syncthreads();

    #pragma unroll
    for (int i = 0; i < 2; i++)
        #pragma unroll
        for (int j = 0; j < 4; j++)
            wmma::store_matrix_sync(Csh + (wm * 32 + i * 16) * LDC_S + wn * 64 + j * 16,
                                    fc[i][j], LDC_S, wmma::mem_row_major);
    __syncthreads();

    float* O = Obase + (size_t)bz * C_ * N_;
    const float* X = Xres + (size_t)bz * C_ * N_;
    #pragma unroll
    for (int it = 0; it < 32; it++) {
        int v = tid + it * 256;            // pair index
        int r = v >> 6, c2 = (v & 63) * 2;
        int gr = m0 + r, gc = n0 + c2;
        float2 xr = *(const float2*)(X + (size_t)gr * N_ + gc);
        float bb = bias[gr];
        float2 o;
        o.x = xr.x + Csh[r * LDC_S + c2]     + bb;
        o.y = xr.y + Csh[r * LDC_S + c2 + 1] + bb;
        *(float2*)(O + (size_t)gr * N_ + gc) = o;
    }
}

// ---------------- flash PTX helpers ----------------
__device__ __forceinline__ void ldsm4(unsigned addr, unsigned& r0, unsigned& r1,
                                      unsigned& r2, unsigned& r3) {
    asm volatile("ldmatrix.sync.aligned.m8n8.x4.shared.b16 {%0,%1,%2,%3}, [%4];"
                 : "=r"(r0), "=r"(r1), "=r"(r2), "=r"(r3) : "r"(addr));
}
__device__ __forceinline__ void ldsm4t(unsigned addr, unsigned& r0, unsigned& r1,
                                       unsigned& r2, unsigned& r3) {
    asm volatile("ldmatrix.sync.aligned.m8n8.x4.trans.shared.b16 {%0,%1,%2,%3}, [%4];"
                 : "=r"(r0), "=r"(r1), "=r"(r2), "=r"(r3) : "r"(addr));
}
__device__ __forceinline__ void mma16816(float* c, unsigned a0, unsigned a1, unsigned a2,
                                         unsigned a3, unsigned b0, unsigned b1) {
    asm volatile("mma.sync.aligned.m16n8k16.row.col.f32.bf16.bf16.f32 "
                 "{%0,%1,%2,%3}, {%4,%5,%6,%7}, {%8,%9}, {%0,%1,%2,%3};"
                 : "+f"(c[0]), "+f"(c[1]), "+f"(c[2]), "+f"(c[3])
                 : "r"(a0), "r"(a1), "r"(a2), "r"(a3), "r"(b0), "r"(b1));
}

// ---------------- fused flash attention (R14, byte-identical) --------------
#define FD   256
#define FBR  128
#define FBC  64
#define FLDQ 264
#define FNIT (N_ / FBC)
#define FSMEM (3 * 128 * FLDQ * 2)

__global__ void __launch_bounds__(256, 1)
flash_attn(const __nv_bfloat16* __restrict__ Qg,
           const __nv_bfloat16* __restrict__ Kg,
           const __nv_bfloat16* __restrict__ Vg,
           __nv_bfloat16* __restrict__ Hg) {
    extern __shared__ __align__(128) unsigned char smem[];
    __nv_bfloat16* Qs = (__nv_bfloat16*)smem;
    __nv_bfloat16* Ks = Qs + FBR * FLDQ;
    __nv_bfloat16* Vs = Ks + 2 * FBC * FLDQ;

    const int tid  = threadIdx.x;
    const int w    = tid >> 5;
    const int lane = tid & 31;
    const int n0   = blockIdx.x * FBR;
    const int b    = blockIdx.y;

    const __nv_bfloat16* Qp = Qg + ((size_t)b * N_ + n0) * FD;
    const __nv_bfloat16* Kp = Kg + (size_t)b * N_ * FD;
    const __nv_bfloat16* Vp = Vg + (size_t)b * N_ * FD;

    #pragma unroll
    for (int t = 0; t < 16; t++) {
        int id = tid + t * 256;
        int r = id >> 5, c = id & 31;
        *(uint4*)(Qs + r * FLDQ + c * 8) = *(const uint4*)(Qp + (size_t)r * FD + c * 8);
    }

    const unsigned qbase = smem_u32(Qs + (w * 16 + (lane & 15)) * FLDQ + ((lane >> 4) << 3));
    const unsigned kbase = smem_u32(Ks + (lane & 7) * FLDQ + ((lane >> 3) << 3));
    const unsigned vbase = smem_u32(Vs + (lane & 15) * FLDQ + ((lane >> 4) << 3));
    const unsigned bufstep = FBC * FLDQ * 2;

    float oacc[32][4];
    #pragma unroll
    for (int t = 0; t < 32; t++)
        #pragma unroll
        for (int i = 0; i < 4; i++) oacc[t][i] = 0.f;
    float l0 = 0.f, l1 = 0.f;

    auto loadKV = [&](int j, int buf) {
        const __nv_bfloat16* kp = Kp + (size_t)j * FBC * FD;
        const __nv_bfloat16* vp = Vp + (size_t)j * FBC * FD;
        __nv_bfloat16* kd = Ks + buf * FBC * FLDQ;
        __nv_bfloat16* vd = Vs + buf * FBC * FLDQ;
        #pragma unroll
        for (int t = 0; t < 8; t++) {
            int id = tid + t * 256;
            int r = id >> 5, c = id & 31;
            cp_async16(kd + r * FLDQ + c * 8, kp + (size_t)r * FD + c * 8);
            cp_async16(vd + r * FLDQ + c * 8, vp + (size_t)r * FD + c * 8);
        }
        cp_commit();
    };

    loadKV(0, 0);

    for (int j = 0; j < FNIT; j++) {
        asm volatile("cp.async.wait_group 0;\n" ::: "memory");
        __syncthreads();
        if (j + 1 < FNIT) loadKV(j + 1, (j + 1) & 1);

        const unsigned kb = kbase + (unsigned)(j & 1) * bufstep;
        const unsigned vb = vbase + (unsigned)(j & 1) * bufstep;

        float sacc[8][4];
        #pragma unroll
        for (int t = 0; t < 8; t++)
            #pragma unroll
            for (int i = 0; i < 4; i++) sacc[t][i] = 0.f;

        {
            unsigned kf[2][4];
            ldsm4(kb, kf[0][0], kf[0][1], kf[0][2], kf[0][3]);
            #pragma unroll
            for (int kk2 = 0; kk2 < 8; kk2++) {
                unsigned qa0, qa1, qa2, qa3, qc0, qc1, qc2, qc3;
                ldsm4(qbase + (unsigned)(2 * kk2) * 32u, qa0, qa1, qa2, qa3);
                ldsm4(qbase + (unsigned)(2 * kk2 + 1) * 32u, qc0, qc1, qc2, qc3);
                #pragma unroll
                for (int jt = 0; jt < 8; jt++) {
                    int cur = (kk2 * 8 + jt) & 1;
                    int nxt = cur ^ 1;
                    if (jt < 7) {
                        ldsm4(kb + (unsigned)(jt + 1) * (8u * FLDQ * 2u)
                                 + (unsigned)kk2 * 64u,
                              kf[nxt][0], kf[nxt][1], kf[nxt][2], kf[nxt][3]);
                    } else if (kk2 < 7) {
                        ldsm4(kb + (unsigned)(kk2 + 1) * 64u,
                              kf[nxt][0], kf[nxt][1], kf[nxt][2], kf[nxt][3]);
                    }
                    mma16816(sacc[jt], qa0, qa1, qa2, qa3, kf[cur][0], kf[cur][1]);
                    mma16816(sacc[jt], qc0, qc1, qc2, qc3, kf[cur][2], kf[cur][3]);
                }
            }
        }

        unsigned pa[4][4];
        #pragma unroll
        for (int kk = 0; kk < 4; kk++) {
            #pragma unroll
            for (int tt = 0; tt < 2; tt++) {
                int jt = 2 * kk + tt;
                float e0 = __expf(sacc[jt][0]);
                float e1 = __expf(sacc[jt][1]);
                float e2 = __expf(sacc[jt][2]);
                float e3 = __expf(sacc[jt][3]);
                l0 += e0 + e1;
                l1 += e2 + e3;
                pa[kk][tt * 2 + 0] = pack_bf16(e0, e1);
                pa[kk][tt * 2 + 1] = pack_bf16(e2, e3);
            }
        }

        {
            unsigned vf[2][4];
            ldsm4t(vb, vf[0][0], vf[0][1], vf[0][2], vf[0][3]);
            #pragma unroll
            for (int kk = 0; kk < 4; kk++) {
                #pragma unroll
                for (int jt = 0; jt < 16; jt++) {
                    int cur = (kk * 16 + jt) & 1;
                    int nxt = cur ^ 1;
                    if (jt < 15) {
                        ldsm4t(vb + (unsigned)kk * (16u * FLDQ * 2u)
                                  + (unsigned)(jt + 1) * 32u,
                               vf[nxt][0], vf[nxt][1], vf[nxt][2], vf[nxt][3]);
                    } else if (kk < 3) {
                        ldsm4t(vb + (unsigned)(kk + 1) * (16u * FLDQ * 2u),
                               vf[nxt][0], vf[nxt][1], vf[nxt][2], vf[nxt][3]);
                    }
                    mma16816(oacc[2 * jt],     pa[kk][0], pa[kk][1], pa[kk][2], pa[kk][3],
                             vf[cur][0], vf[cur][1]);
                    mma16816(oacc[2 * jt + 1], pa[kk][0], pa[kk][1], pa[kk][2], pa[kk][3],
                             vf[cur][2], vf[cur][3]);
                }
            }
        }
    }

    l0 += __shfl_xor_sync(0xffffffffu, l0, 1);
    l0 += __shfl_xor_sync(0xffffffffu, l0, 2);
    l1 += __shfl_xor_sync(0xffffffffu, l1, 1);
    l1 += __shfl_xor_sync(0xffffffffu, l1, 2);
    float inv0 = 1.f / l0;
    float inv1 = 1.f / l1;

    int gr0 = n0 + w * 16 + (lane >> 2);
    int gr1 = gr0 + 8;
    int cb  = 2 * (lane & 3);
    __nv_bfloat16* Hp = Hg + (size_t)b * N_ * C_;
    #pragma unroll
    for (int t = 0; t < 32; t++) {
        int col = t * 8 + cb;
        *(unsigned*)&Hp[(size_t)gr0 * C_ + col] = pack_bf16(oacc[t][0] * inv0, oacc[t][1] * inv0);
        *(unsigned*)&Hp[(size_t)gr1 * C_ + col] = pack_bf16(oacc[t][2] * inv1, oacc[t][3] * inv1);
    }
}

// ---------------- launch ----------------
extern "C" void kernel_launch(void* const* d_in, const int* in_sizes, int n_in,
                              void* d_out, int out_size) {
    const float* x   = (const float*)d_in[0];
    const float* gsc = (const float*)d_in[1];
    const float* gbi = (const float*)d_in[2];
    const float* wq  = (const float*)d_in[3];
    const float* bq  = (const float*)d_in[4];
    const float* wk  = (const float*)d_in[5];
    const float* bk  = (const float*)d_in[6];
    const float* wv  = (const float*)d_in[7];
    const float* bv  = (const float*)d_in[8];
    const float* wp  = (const float*)d_in[9];
    const float* bp  = (const float*)d_in[10];

    void *p_hn, *p_Q, *p_K, *p_V, *p_H, *p_wqkv, *p_wp;
    cudaGetSymbolAddress(&p_hn, g_hn);
    cudaGetSymbolAddress(&p_Q, g_Q);
    cudaGetSymbolAddress(&p_K, g_K);
    cudaGetSymbolAddress(&p_V, g_V);
    cudaGetSymbolAddress(&p_H, g_H);
    cudaGetSymbolAddress(&p_wqkv, g_wqkv);
    cudaGetSymbolAddress(&p_wp, g_wp);

    static int smem_set = 0;
    if (!smem_set) {
        cudaFuncSetAttribute(flash_attn, cudaFuncAttributeMaxDynamicSharedMemorySize, FSMEM);
        cudaFuncSetAttribute(groupnorm_kernel, cudaFuncAttributeMaxDynamicSharedMemorySize,
                             8 * N_ * 4);
        cudaFuncSetAttribute(gemm_qkv, cudaFuncAttributeMaxDynamicSharedMemorySize, GSMEM);
        cudaFuncSetAttribute(gemm_proj, cudaFuncAttributeMaxDynamicSharedMemorySize, GSMEM);
        smem_set = 1;
    }

    convert_weights<<<(C_ * C_ + 255) / 256, 256>>>(wq, wk, wv, wp);
    groupnorm_kernel<<<B_ * GROUPS_, 1024, 8 * N_ * 4>>>(x, gsc, gbi);

    // fused QKV: 128x128-tile pipelined GEMM over packed [768,256] weights
    dim3 gqkv((B_ * N_) / BM, (3 * C_) / BN);
    gemm_qkv<<<gqkv, 256, GSMEM>>>(
        (const __nv_bfloat16*)p_hn, (const __nv_bfloat16*)p_wqkv,
        (__nv_bfloat16*)p_Q, (__nv_bfloat16*)p_K, (__nv_bfloat16*)p_V, bq, bk, bv);

    // fused attention -> H bf16 directly
    dim3 gflash(N_ / FBR, B_);
    flash_attn<<<gflash, 256, FSMEM>>>(
        (const __nv_bfloat16*)p_Q, (const __nv_bfloat16*)p_K, (const __nv_bfloat16*)p_V,
        (__nv_bfloat16*)p_H);

    // out[b,o,n] = x + Wproj @ H^T + bproj  (fp32, direct to d_out)
    dim3 gpr(C_ / BM, N_ / BN, B_);
    gemm_proj<<<gpr, 256, GSMEM>>>(
        (const __nv_bfloat16*)p_wp, (const __nv_bfloat16*)p_H, (float*)d_out, bp, x);
}